// round 14
// baseline (speedup 1.0000x reference)
#include <cuda_runtime.h>
#include <cuda_bf16.h>
#include <math.h>
#include <stdint.h>

#define B_    4
#define NQ_   1024
#define NKV_  2048
#define D_    288

__device__ constexpr int   GRADEA[16] = {0,1,1,1,1,2,2,2,2,2,2,3,3,3,3,4};
__device__ constexpr float METRICA[16] = {1.f,1.f,-1.f,-1.f,-1.f,-1.f,-1.f,-1.f,
                                          1.f,1.f, 1.f, 1.f, 1.f, 1.f,-1.f,-1.f};
__constant__ int GRADE_RT[16] = {0,1,1,1,1,2,2,2,2,2,2,3,3,3,3,4};

// scratch
__device__ __align__(1024) float QB[(size_t)B_*8*NQ_*D_];
__device__ __align__(1024) float KB[(size_t)B_*8*NKV_*D_];
__device__ __align__(1024) float VB[(size_t)B_*8*NKV_*D_];
__device__ __align__(1024) float OB[(size_t)B_*NQ_*8*D_];
// packed bf16x2 fragment images
__device__ __align__(1024) uint32_t QFG[(size_t)32*8*36864];
__device__ __align__(1024) uint32_t KFG[(size_t)32*32*3*6144];
__device__ __align__(1024) uint32_t VFG[(size_t)32*32*3*6144];

__device__ __forceinline__ uint32_t pk2b(float lo, float hi) {
    __nv_bfloat162 h = __floats2bfloat162_rn(lo, hi);
    return *(uint32_t*)&h;
}
__device__ __forceinline__ float bf16res(float x) {
    return x - __bfloat162float(__float2bfloat16_rn(x));
}
#define MMA16(c,a0,a1,a2,a3,b0,b1) \
    asm volatile("mma.sync.aligned.m16n8k16.row.col.f32.bf16.bf16.f32 " \
        "{%0,%1,%2,%3},{%4,%5,%6,%7},{%8,%9},{%0,%1,%2,%3};" \
        : "+f"((c)[0]),"+f"((c)[1]),"+f"((c)[2]),"+f"((c)[3]) \
        : "r"(a0),"r"(a1),"r"(a2),"r"(a3),"r"(b0),"r"(b1))

__device__ __forceinline__ uint32_t smem_u32(const void* p) {
    uint32_t a;
    asm("{ .reg .u64 t; cvta.to.shared.u64 t, %1; cvt.u32.u64 %0, t; }" : "=r"(a) : "l"(p));
    return a;
}
__device__ __forceinline__ void bulkld(uint32_t sdst, const void* gsrc, uint32_t mbar, uint32_t bytes) {
    asm volatile("cp.async.bulk.shared::cluster.global.mbarrier::complete_tx::bytes [%0], [%1], %2, [%3];"
        :: "r"(sdst), "l"(gsrc), "r"(bytes), "r"(mbar) : "memory");
}
#define MB_INIT(mb, c)    asm volatile("mbarrier.init.shared.b64 [%0], %1;" :: "r"(mb), "r"(c) : "memory")
#define MB_EXPECT(mb, nb) asm volatile("mbarrier.arrive.expect_tx.shared.b64 _, [%0], %1;" :: "r"(mb), "r"(nb) : "memory")
#define MB_WAIT(mb, par) do { \
    asm volatile("{\n\t.reg .pred P1;\n\tWL_%=:\n\t" \
        "mbarrier.try_wait.parity.acquire.cta.shared::cta.b64 P1, [%0], %1, 0x989680;\n\t" \
        "@P1 bra.uni WD_%=;\n\tbra.uni WL_%=;\n\tWD_%=:\n\t}" \
        :: "r"(mb), "r"(par) : "memory"); } while (0)

// ============================================================================
// proj2: token-per-lane, channels-per-warp, 2-channel blocking.
// grid (256, 3), 128 threads.
// ============================================================================
__global__ void proj2_kernel(
    const float* __restrict__ mv_q,  const float* __restrict__ s_q,
    const float* __restrict__ mv_kv, const float* __restrict__ s_kv,
    const float* __restrict__ wq_mv, const float* __restrict__ wq_s2mv,
    const float* __restrict__ wq_m2s, const float* __restrict__ wq_s2s,
    const float* __restrict__ bq_mv, const float* __restrict__ bq_s,
    const float* __restrict__ wk_mv, const float* __restrict__ wk_s2mv,
    const float* __restrict__ wk_m2s, const float* __restrict__ wk_s2s,
    const float* __restrict__ bk_mv, const float* __restrict__ bk_s,
    const float* __restrict__ wv_mv, const float* __restrict__ wv_s2mv,
    const float* __restrict__ wv_m2s, const float* __restrict__ wv_s2s,
    const float* __restrict__ bv_mv, const float* __restrict__ bv_s)
{
    __shared__ float xT[256 * 33];
    __shared__ float xsT[32 * 33];

    const int sel = blockIdx.y;
    const int ntok = (sel == 0) ? NQ_ : NKV_;
    const int ntiles = (B_ * ntok) / 32;
    const int tile = blockIdx.x;
    if (tile >= ntiles) return;

    const float* x_mv = (sel == 0) ? mv_q : mv_kv;
    const float* x_s  = (sel == 0) ? s_q  : s_kv;
    const float* w_mv    = (sel == 0) ? wq_mv  : (sel == 1) ? wk_mv  : wv_mv;
    const float* w_s2mv  = (sel == 0) ? wq_s2mv: (sel == 1) ? wk_s2mv: wv_s2mv;
    const float* w_mvs2s = (sel == 0) ? wq_m2s : (sel == 1) ? wk_m2s : wv_m2s;
    const float* w_s2s   = (sel == 0) ? wq_s2s : (sel == 1) ? wk_s2s : wv_s2s;
    const float* b_mv    = (sel == 0) ? bq_mv  : (sel == 1) ? bk_mv  : bv_mv;
    const float* b_s     = (sel == 0) ? bq_s   : (sel == 1) ? bk_s   : bv_s;
    float* out = (sel == 0) ? QB : (sel == 1) ? KB : VB;
    const int applyMetric = (sel == 1);

    const int tid = threadIdx.x, w = tid >> 5, lane = tid & 31;
    const int t0 = tile * 32;
    const int b = t0 / ntok, n0 = t0 % ntok;

    {
        const float4* src = (const float4*)(x_mv + (size_t)t0 * 256);
#pragma unroll
        for (int i = 0; i < 16; ++i) {
            int f4 = i * 128 + tid;
            int tok = f4 >> 6, feat4 = f4 & 63;
            float4 v = src[f4];
            xT[(feat4 * 4 + 0) * 33 + tok] = v.x;
            xT[(feat4 * 4 + 1) * 33 + tok] = v.y;
            xT[(feat4 * 4 + 2) * 33 + tok] = v.z;
            xT[(feat4 * 4 + 3) * 33 + tok] = v.w;
        }
        const float* ssrc = x_s + (size_t)t0 * 32;
#pragma unroll
        for (int i = 0; i < 8; ++i) {
            int idx = i * 128 + tid;
            int tok = idx >> 5, s = idx & 31;
            xsT[s * 33 + tok] = ssrc[tok * 32 + s];
        }
    }
    __syncthreads();

    // mv outputs: 2-channel blocking (one xT LDS feeds 2 FMAs)
    for (int oc = 0; oc < 32; oc += 2) {
        const int o0 = w * 32 + oc;
        const float* wr0 = w_mv + o0 * 80;
        const float* wr1 = wr0 + 80;
        float a00 = b_mv[o0], a10 = b_mv[o0 + 1];
        const float* ws0 = w_s2mv + o0 * 32;
#pragma unroll
        for (int s = 0; s < 32; ++s) {
            float xv = xsT[s * 33 + lane];
            a00 += xv * ws0[s];
            a10 += xv * ws0[32 + s];
        }
        const int head0 = o0 & 7, hid0 = o0 >> 3;
        const int head1 = (o0 + 1) & 7, hid1 = (o0 + 1) >> 3;
        float* op0 = out + ((size_t)(b * 8 + head0) * ntok + (n0 + lane)) * D_ + hid0 * 16;
        float* op1 = out + ((size_t)(b * 8 + head1) * ntok + (n0 + lane)) * D_ + hid1 * 16;
#pragma unroll
        for (int x = 0; x < 16; ++x) {
            float acc0 = (x == 0) ? a00 : 0.f;
            float acc1 = (x == 0) ? a10 : 0.f;
            const int g = GRADEA[x];
#pragma unroll
            for (int i = 0; i < 16; ++i) {
                float xv = xT[(i * 16 + x) * 33 + lane];
                acc0 += xv * wr0[i * 5 + g];
                acc1 += xv * wr1[i * 5 + g];
            }
            if (applyMetric) { acc0 *= METRICA[x]; acc1 *= METRICA[x]; }
            op0[x] = acc0;
            op1[x] = acc1;
        }
    }

    // scalar outputs: 2-channel blocking
    for (int oc = 0; oc < 64; oc += 2) {
        const int o0 = w * 64 + oc;
        float y0 = b_s[o0], y1 = b_s[o0 + 1];
        const float* wm0 = w_mvs2s + o0 * 16;
#pragma unroll
        for (int i = 0; i < 16; ++i) {
            float xv = xT[(i * 16) * 33 + lane];
            y0 += xv * wm0[i];
            y1 += xv * wm0[16 + i];
        }
        const float* ws0 = w_s2s + o0 * 32;
#pragma unroll
        for (int s = 0; s < 32; ++s) {
            float xv = xsT[s * 33 + lane];
            y0 += xv * ws0[s];
            y1 += xv * ws0[32 + s];
        }
        const int head0 = o0 & 7, hid0 = o0 >> 3;
        const int head1 = (o0 + 1) & 7, hid1 = (o0 + 1) >> 3;
        out[((size_t)(b * 8 + head0) * ntok + (n0 + lane)) * D_ + 256 + hid0] = y0;
        out[((size_t)(b * 8 + head1) * ntok + (n0 + lane)) * D_ + 256 + hid1] = y1;
    }
}

// ============================================================================
// repackQ: grid (8, 32), 256 thr (unchanged from R13).
// ============================================================================
#define STGS 292
__global__ void repackQ_kernel()
{
    extern __shared__ float ss[];
    const int qt = blockIdx.x, bh = blockIdx.y, tid = threadIdx.x;
    const float SCALE = 0.0589255650988789f;
    const float* src = QB + ((size_t)bh * NQ_ + qt * 128) * D_;
#pragma unroll
    for (int i = 0; i < 36; ++i) {
        int idx = i * 256 + tid, row = idx / 72, c4 = idx % 72;
        float4 v = *(const float4*)(src + (size_t)row * D_ + c4 * 4);
        float* d = ss + row * STGS + c4 * 4;
        d[0] = v.x; d[1] = v.y; d[2] = v.z; d[3] = v.w;
    }
    __syncthreads();
    uint32_t* dst = QFG + (size_t)(bh * 8 + qt) * 36864;
#pragma unroll
    for (int i = 0; i < 18; ++i) {
        int gidx = i * 256 + tid;
        int ms = gidx / 576, rem = gidx % 576, ks = rem >> 5, lane = rem & 31;
        int g = lane >> 2, t = lane & 3;
        int r0 = ms * 16 + g, c0 = ks * 16 + 2 * t;
        float v[8];
        v[0] = ss[r0 * STGS + c0] * SCALE;        v[1] = ss[r0 * STGS + c0 + 1] * SCALE;
        v[2] = ss[(r0+8) * STGS + c0] * SCALE;    v[3] = ss[(r0+8) * STGS + c0 + 1] * SCALE;
        v[4] = ss[r0 * STGS + c0 + 8] * SCALE;    v[5] = ss[r0 * STGS + c0 + 9] * SCALE;
        v[6] = ss[(r0+8) * STGS + c0 + 8] * SCALE;v[7] = ss[(r0+8) * STGS + c0 + 9] * SCALE;
        uint4 hi = { pk2b(v[0],v[1]), pk2b(v[2],v[3]), pk2b(v[4],v[5]), pk2b(v[6],v[7]) };
        uint4 lo = { pk2b(bf16res(v[0]),bf16res(v[1])), pk2b(bf16res(v[2]),bf16res(v[3])),
                     pk2b(bf16res(v[4]),bf16res(v[5])), pk2b(bf16res(v[6]),bf16res(v[7])) };
        *(uint4*)(dst + (size_t)gidx * 4)          = hi;
        *(uint4*)(dst + 18432 + (size_t)gidx * 4)  = lo;
    }
}

// ============================================================================
// repackKV: K hi+lo; V hi+lo. grid (32, 32, 2), 256 thr (unchanged).
// ============================================================================
__global__ void repackKV_kernel()
{
    extern __shared__ float ss[];
    const int kt = blockIdx.x, bh = blockIdx.y, zv = blockIdx.z, tid = threadIdx.x;
    const float* src = (zv ? VB : KB) + ((size_t)bh * NKV_ + kt * 64) * D_;
#pragma unroll
    for (int i = 0; i < 18; ++i) {
        int idx = i * 256 + tid, row = idx / 72, c4 = idx % 72;
        float4 v = *(const float4*)(src + (size_t)row * D_ + c4 * 4);
        float* d = ss + row * STGS + c4 * 4;
        d[0] = v.x; d[1] = v.y; d[2] = v.z; d[3] = v.w;
    }
    __syncthreads();
    uint32_t* dst = (zv ? VFG : KFG) + (size_t)(bh * 32 + kt) * 3 * 6144;
    if (!zv) {
#pragma unroll
        for (int i = 0; i < 18; ++i) {
            int e = i * 256 + tid;
            int c = e / 1536, rem = e % 1536;
            int n = rem / 192, rem2 = rem % 192, ksl = rem2 >> 5, lane = rem2 & 31;
            int g = lane >> 2, t = lane & 3;
            int key = n * 8 + g, d0 = c * 96 + ksl * 16 + 2 * t;
            float x0 = ss[key * STGS + d0],     x1 = ss[key * STGS + d0 + 1];
            float x2 = ss[key * STGS + d0 + 8], x3 = ss[key * STGS + d0 + 9];
            uint32_t* ch = dst + (size_t)c * 6144;
            int go = ((n * 6 + ksl) * 32 + lane) * 2;
            *(uint2*)(ch + go)        = make_uint2(pk2b(x0, x1), pk2b(x2, x3));
            *(uint2*)(ch + 3072 + go) = make_uint2(pk2b(bf16res(x0), bf16res(x1)),
                                                   pk2b(bf16res(x2), bf16res(x3)));
        }
    } else {
#pragma unroll
        for (int i = 0; i < 18; ++i) {
            int e = i * 256 + tid;
            int c = e / 1536, rem = e % 1536;
            int ntl = rem / 128, rem2 = rem % 128, ks = rem2 >> 5, lane = rem2 & 31;
            int g = lane >> 2, t = lane & 3;
            int key0 = ks * 16 + 2 * t, d = c * 96 + ntl * 8 + g;
            float x0 = ss[key0 * STGS + d],       x1 = ss[(key0+1) * STGS + d];
            float x2 = ss[(key0+8) * STGS + d],   x3 = ss[(key0+9) * STGS + d];
            uint32_t* ch = dst + (size_t)c * 6144;
            int go = ((ntl * 4 + ks) * 32 + lane) * 2;
            *(uint2*)(ch + go)        = make_uint2(pk2b(x0, x1), pk2b(x2, x3));
            *(uint2*)(ch + 3072 + go) = make_uint2(pk2b(bf16res(x0), bf16res(x1)),
                                                   pk2b(bf16res(x2), bf16res(x3)));
        }
    }
}

// ============================================================================
// attn8: register-resident FA2, split-bf16 — unchanged (R10/R13 config).
// ============================================================================
#define SM_BYTES (147456 + 3 * 24576 + 64)

__global__ __launch_bounds__(256, 1) void attn8_kernel()
{
    extern __shared__ uint32_t smu[];
    uint32_t* Qh = smu;
    uint32_t* Ql = smu + 18432;
    uint32_t* bufs[3] = { smu + 36864, smu + 43008, smu + 49152 };

    const int tid = threadIdx.x, bh = blockIdx.y, qt = blockIdx.x;
    const int w = tid >> 5, lane = tid & 31, g = lane >> 2, t = lane & 3;

    const uint32_t sb = smem_u32(smu);
    const uint32_t mbase = sb + (36864 + 3 * 6144) * 4;
    const uint32_t mbQ = mbase + 24;

    const uint32_t* KFb = KFG + (size_t)(bh * 32) * 3 * 6144;
    const uint32_t* VFb = VFG + (size_t)(bh * 32) * 3 * 6144;

    if (tid == 0) {
        MB_INIT(mbase + 0, 1); MB_INIT(mbase + 8, 1); MB_INIT(mbase + 16, 1);
        MB_INIT(mbQ, 1);
    }
    __syncthreads();
    if (tid == 0) {
        MB_EXPECT(mbQ, 147456u);
        bulkld(sb, QFG + (size_t)(bh * 8 + qt) * 36864, mbQ, 147456u);
#pragma unroll
        for (int c = 0; c < 3; ++c) {
            MB_EXPECT(mbase + 8 * c, 24576u);
            bulkld(sb + (36864 + c * 6144) * 4, KFb + c * 6144, mbase + 8 * c, 24576u);
        }
    }

    float O[3][12][4];
#pragma unroll
    for (int c = 0; c < 3; ++c)
#pragma unroll
        for (int n = 0; n < 12; ++n)
#pragma unroll
            for (int k = 0; k < 4; ++k) O[c][n][k] = 0.f;
    float mA = -1e30f, mB = -1e30f, lA = 0.f, lB = 0.f;

    MB_WAIT(mbQ, 0);

    for (int kt = 0; kt < 32; ++kt) {
        const uint32_t* VFt = VFb + (size_t)kt * 3 * 6144;
        const uint32_t* KFn = KFb + (size_t)(kt + 1) * 3 * 6144;

        float cS[8][4];
#pragma unroll
        for (int n = 0; n < 8; ++n)
#pragma unroll
            for (int k = 0; k < 4; ++k) cS[n][k] = 0.f;

#pragma unroll
        for (int c = 0; c < 3; ++c) {
            MB_WAIT(mbase + 8 * c, 0);
            const uint32_t* buf = bufs[c];
#pragma unroll
            for (int ksl = 0; ksl < 6; ++ksl) {
                const int ksg = c * 6 + ksl;
                uint4 Ah = *(const uint4*)(Qh + ((w * 18 + ksg) * 32 + lane) * 4);
                uint4 Al = *(const uint4*)(Ql + ((w * 18 + ksg) * 32 + lane) * 4);
#pragma unroll
                for (int n = 0; n < 8; ++n) {
                    uint2 bh2 = *(const uint2*)(buf + ((n * 6 + ksl) * 32 + lane) * 2);
                    uint2 bl2 = *(const uint2*)(buf + 3072 + ((n * 6 + ksl) * 32 + lane) * 2);
                    MMA16(cS[n], Ah.x, Ah.y, Ah.z, Ah.w, bh2.x, bh2.y);
                    MMA16(cS[n], Al.x, Al.y, Al.z, Al.w, bh2.x, bh2.y);
                    MMA16(cS[n], Ah.x, Ah.y, Ah.z, Ah.w, bl2.x, bl2.y);
                }
            }
            __syncthreads();
            if (tid == 0) {
                MB_EXPECT(mbase + 8 * c, 24576u);
                bulkld(sb + (36864 + c * 6144) * 4, VFt + c * 6144, mbase + 8 * c, 24576u);
            }
        }

        float mxA = -1e30f, mxB = -1e30f;
#pragma unroll
        for (int n = 0; n < 8; ++n) {
            mxA = fmaxf(mxA, fmaxf(cS[n][0], cS[n][1]));
            mxB = fmaxf(mxB, fmaxf(cS[n][2], cS[n][3]));
        }
        mxA = fmaxf(mxA, __shfl_xor_sync(0xffffffffu, mxA, 1));
        mxA = fmaxf(mxA, __shfl_xor_sync(0xffffffffu, mxA, 2));
        mxB = fmaxf(mxB, __shfl_xor_sync(0xffffffffu, mxB, 1));
        mxB = fmaxf(mxB, __shfl_xor_sync(0xffffffffu, mxB, 2));
        const float mnA = fmaxf(mA, mxA), mnB = fmaxf(mB, mxB);
        const float alA = __expf(mA - mnA), alB = __expf(mB - mnB);
        mA = mnA; mB = mnB;

        uint32_t PhT[8], PhB[8], PlT[8], PlB[8];
        float sA = 0.f, sB = 0.f;
#pragma unroll
        for (int n = 0; n < 8; ++n) {
            float e0 = __expf(cS[n][0] - mnA), e1 = __expf(cS[n][1] - mnA);
            float e2 = __expf(cS[n][2] - mnB), e3 = __expf(cS[n][3] - mnB);
            sA += e0 + e1; sB += e2 + e3;
            PhT[n] = pk2b(e0, e1); PhB[n] = pk2b(e2, e3);
            PlT[n] = pk2b(bf16res(e0), bf16res(e1));
            PlB[n] = pk2b(bf16res(e2), bf16res(e3));
        }
        sA += __shfl_xor_sync(0xffffffffu, sA, 1);
        sA += __shfl_xor_sync(0xffffffffu, sA, 2);
        sB += __shfl_xor_sync(0xffffffffu, sB, 1);
        sB += __shfl_xor_sync(0xffffffffu, sB, 2);
        lA = lA * alA + sA;
        lB = lB * alB + sB;
#pragma unroll
        for (int c = 0; c < 3; ++c)
#pragma unroll
            for (int n = 0; n < 12; ++n) {
                O[c][n][0] *= alA; O[c][n][1] *= alA;
                O[c][n][2] *= alB; O[c][n][3] *= alB;
            }

#pragma unroll
        for (int c = 0; c < 3; ++c) {
            MB_WAIT(mbase + 8 * c, 1);
            const uint32_t* buf = bufs[c];
#pragma unroll
            for (int ks = 0; ks < 4; ++ks) {
                uint32_t ah0 = PhT[2*ks], ah1 = PhB[2*ks], ah2 = PhT[2*ks+1], ah3 = PhB[2*ks+1];
                uint32_t al0 = PlT[2*ks], al1 = PlB[2*ks], al2 = PlT[2*ks+1], al3 = PlB[2*ks+1];
#pragma unroll
                for (int ntl = 0; ntl < 12; ++ntl) {
                    uint2 vh = *(const uint2*)(buf + ((ntl * 4 + ks) * 32 + lane) * 2);
                    uint2 vl = *(const uint2*)(buf + 3072 + ((ntl * 4 + ks) * 32 + lane) * 2);
                    MMA16(O[c][ntl], ah0, ah1, ah2, ah3, vh.x, vh.y);
                    MMA16(O[c][ntl], al0, al1, al2, al3, vh.x, vh.y);
                    MMA16(O[c][ntl], ah0, ah1, ah2, ah3, vl.x, vl.y);
                }
            }
            __syncthreads();
            if (kt < 31 && tid == 0) {
                MB_EXPECT(mbase + 8 * c, 24576u);
                bulkld(sb + (36864 + c * 6144) * 4, KFn + c * 6144, mbase + 8 * c, 24576u);
            }
        }
    }

    const float liA = 1.f / lA, liB = 1.f / lB;
    const int b = bh >> 3, hh = bh & 7;
    const int rA = qt * 128 + w * 16 + g, rB = rA + 8;
    float* oA = OB + (((size_t)(b * NQ_ + rA)) * 8 + hh) * D_;
    float* oB = OB + (((size_t)(b * NQ_ + rB)) * 8 + hh) * D_;
#pragma unroll
    for (int c = 0; c < 3; ++c)
#pragma unroll
        for (int n = 0; n < 12; ++n) {
            int d = c * 96 + n * 8 + 2 * t;
            *(float2*)(oA + d) = make_float2(O[c][n][0] * liA, O[c][n][1] * liA);
            *(float2*)(oB + d) = make_float2(O[c][n][2] * liB, O[c][n][3] * liB);
        }
}

// ============================================================================
// outproj3: 8-token tiles, 256 threads, grid 512.
// Loop-swapped mv phase: one xT LDS feeds 8 FMAs; wo_mv staged in smem.
// ============================================================================
#define OP_SMEM ((2304 * 9 + 128 + 10240) * 4)

__global__ void outproj3_kernel(const float* __restrict__ wo_mv, const float* __restrict__ wo_s2mv,
                                const float* __restrict__ wo_mvs2s, const float* __restrict__ wo_s2s,
                                const float* __restrict__ bo_mv, const float* __restrict__ bo_s,
                                float* __restrict__ d_out)
{
    extern __shared__ float xT[];           // [2304][9]
    float* a0sm = xT + 2304 * 9;            // [tok8][o16]
    float* wsm  = a0sm + 128;               // wo_mv copy: 16*128*5 = 10240 floats
    const int blk = blockIdx.x, tid = threadIdx.x;

    // stage 8 token rows (transposed) + wo_mv
    {
        const float4* src = (const float4*)(OB + (size_t)blk * 8 * 2304);
#pragma unroll
        for (int i = 0; i < 18; ++i) {
            int idx = i * 256 + tid;
            int tok = idx / 576, f4 = idx % 576;
            float4 v = src[(size_t)tok * 576 + f4];
            xT[(f4 * 4 + 0) * 9 + tok] = v.x;
            xT[(f4 * 4 + 1) * 9 + tok] = v.y;
            xT[(f4 * 4 + 2) * 9 + tok] = v.z;
            xT[(f4 * 4 + 3) * 9 + tok] = v.w;
        }
#pragma unroll
        for (int i = 0; i < 10; ++i) {
            int idx = i * 256 + tid;
            if (idx < 2560) ((float4*)wsm)[idx] = ((const float4*)wo_mv)[idx];
        }
    }
    __syncthreads();

    // phase A: a0[tok][o] = bo_mv[o] + sum_s xsc[s]*wo_s2mv[o][s]
    {
        const int tok = tid >> 5, o = (tid >> 1) & 15, part = tid & 1;
        float a = 0.f;
        const float* ws = wo_s2mv + o * 256 + part * 128;
#pragma unroll
        for (int s = 0; s < 128; ++s) {
            int s2 = part * 128 + s;
            int feat = (s2 >> 5) * 288 + 256 + (s2 & 31);
            a += xT[feat * 9 + tok] * ws[s];
        }
        a += __shfl_xor_sync(0xffffffffu, a, 1);
        if (part == 0) a0sm[tok * 16 + o] = a + bo_mv[o];
    }
    __syncthreads();

    const int og = tid >> 3, tok = tid & 7;
    const int tglob = blk * 8 + tok;
    const int x = og & 15, oh = og >> 4;
    const int gg = GRADE_RT[x];

    // mv outputs: all 8 share blade x -> loop-swap, 1 LDS per 8 FMAs
    float y[8];
    int wbase[8];
#pragma unroll
    for (int j = 0; j < 8; ++j) {
        const int o = 2 * j + oh;
        y[j] = (x == 0) ? a0sm[tok * 16 + o] : 0.f;
        wbase[j] = o * 640 + gg;
    }
#pragma unroll 8
    for (int i = 0; i < 128; ++i) {
        const float xv = xT[((i >> 4) * 288 + (i & 15) * 16 + x) * 9 + tok];
        const int wi = i * 5;
#pragma unroll
        for (int j = 0; j < 8; ++j) y[j] += xv * wsm[wbase[j] + wi];
    }
#pragma unroll
    for (int j = 0; j < 8; ++j)
        d_out[(size_t)tglob * 256 + j * 32 + og] = y[j];

    // 1 scalar output per thread (unchanged)
    {
        const int s = og;
        float ysc = bo_s[s];
        const float* wm = wo_mvs2s + s * 128;
#pragma unroll 16
        for (int i = 0; i < 128; ++i) {
            int feat = (i >> 4) * 288 + (i & 15) * 16;
            ysc += xT[feat * 9 + tok] * wm[i];
        }
        const float* ws = wo_s2s + s * 256;
#pragma unroll 16
        for (int s2 = 0; s2 < 256; ++s2) {
            int feat = (s2 >> 5) * 288 + 256 + (s2 & 31);
            ysc += xT[feat * 9 + tok] * ws[s2];
        }
        d_out[(size_t)B_ * NQ_ * 256 + (size_t)tglob * 32 + s] = ysc;
    }
}

extern "C" void kernel_launch(void* const* d_in, const int* in_sizes, int n_in,
                              void* d_out, int out_size)
{
    (void)in_sizes; (void)n_in; (void)out_size;
    const float* mv_kv = (const float*)d_in[0];
    const float* mv_q  = (const float*)d_in[1];
    const float* s_kv  = (const float*)d_in[2];
    const float* s_q   = (const float*)d_in[3];
    const float* wq_mv = (const float*)d_in[4],  *wq_s2mv = (const float*)d_in[5];
    const float* wq_m2s = (const float*)d_in[6], *wq_s2s = (const float*)d_in[7];
    const float* bq_mv = (const float*)d_in[8],  *bq_s = (const float*)d_in[9];
    const float* wk_mv = (const float*)d_in[10], *wk_s2mv = (const float*)d_in[11];
    const float* wk_m2s = (const float*)d_in[12],*wk_s2s = (const float*)d_in[13];
    const float* bk_mv = (const float*)d_in[14], *bk_s = (const float*)d_in[15];
    const float* wv_mv = (const float*)d_in[16], *wv_s2mv = (const float*)d_in[17];
    const float* wv_m2s = (const float*)d_in[18],*wv_s2s = (const float*)d_in[19];
    const float* bv_mv = (const float*)d_in[20], *bv_s = (const float*)d_in[21];
    const float* wo_mv = (const float*)d_in[22], *wo_s2mv = (const float*)d_in[23];
    const float* wo_m2s = (const float*)d_in[24],*wo_s2s = (const float*)d_in[25];
    const float* bo_mv = (const float*)d_in[26], *bo_s = (const float*)d_in[27];

    const int stageQ = 128 * STGS * sizeof(float);
    const int stageKV = 64 * STGS * sizeof(float);
    cudaFuncSetAttribute(repackQ_kernel, cudaFuncAttributeMaxDynamicSharedMemorySize, stageQ);
    cudaFuncSetAttribute(repackKV_kernel, cudaFuncAttributeMaxDynamicSharedMemorySize, stageKV);
    cudaFuncSetAttribute(attn8_kernel, cudaFuncAttributeMaxDynamicSharedMemorySize, SM_BYTES);
    cudaFuncSetAttribute(outproj3_kernel, cudaFuncAttributeMaxDynamicSharedMemorySize, OP_SMEM);

    proj2_kernel<<<dim3(256, 3), 128>>>(
        mv_q, s_q, mv_kv, s_kv,
        wq_mv, wq_s2mv, wq_m2s, wq_s2s, bq_mv, bq_s,
        wk_mv, wk_s2mv, wk_m2s, wk_s2s, bk_mv, bk_s,
        wv_mv, wv_s2mv, wv_m2s, wv_s2s, bv_mv, bv_s);
    repackQ_kernel<<<dim3(8, 32), 256, stageQ>>>();
    repackKV_kernel<<<dim3(32, 32, 2), 256, stageKV>>>();
    attn8_kernel<<<dim3(8, 32), 256, SM_BYTES>>>();
    outproj3_kernel<<<512, 256, OP_SMEM>>>(wo_mv, wo_s2mv, wo_m2s, wo_s2s, bo_mv, bo_s,
                                           (float*)d_out);
}

// round 15
// speedup vs baseline: 1.3125x; 1.3125x over previous
#include <cuda_runtime.h>
#include <cuda_bf16.h>
#include <math.h>
#include <stdint.h>

#define B_    4
#define NQ_   1024
#define NKV_  2048
#define D_    288

__device__ constexpr int   GRADEA[16] = {0,1,1,1,1,2,2,2,2,2,2,3,3,3,3,4};
__device__ constexpr float METRICA[16] = {1.f,1.f,-1.f,-1.f,-1.f,-1.f,-1.f,-1.f,
                                          1.f,1.f, 1.f, 1.f, 1.f, 1.f,-1.f,-1.f};
__constant__ int GRADE_RT[16] = {0,1,1,1,1,2,2,2,2,2,2,3,3,3,3,4};

// scratch
__device__ __align__(1024) float QB[(size_t)B_*8*NQ_*D_];
__device__ __align__(1024) float KB[(size_t)B_*8*NKV_*D_];
__device__ __align__(1024) float VB[(size_t)B_*8*NKV_*D_];
__device__ __align__(1024) float OB[(size_t)B_*NQ_*8*D_];
// packed bf16x2 fragment images
__device__ __align__(1024) uint32_t QFG[(size_t)32*8*36864];
__device__ __align__(1024) uint32_t KFG[(size_t)32*32*3*6144];
__device__ __align__(1024) uint32_t VFG[(size_t)32*32*3*6144];

__device__ __forceinline__ uint32_t pk2b(float lo, float hi) {
    __nv_bfloat162 h = __floats2bfloat162_rn(lo, hi);
    return *(uint32_t*)&h;
}
__device__ __forceinline__ float bf16res(float x) {
    return x - __bfloat162float(__float2bfloat16_rn(x));
}
#define MMA16(c,a0,a1,a2,a3,b0,b1) \
    asm volatile("mma.sync.aligned.m16n8k16.row.col.f32.bf16.bf16.f32 " \
        "{%0,%1,%2,%3},{%4,%5,%6,%7},{%8,%9},{%0,%1,%2,%3};" \
        : "+f"((c)[0]),"+f"((c)[1]),"+f"((c)[2]),"+f"((c)[3]) \
        : "r"(a0),"r"(a1),"r"(a2),"r"(a3),"r"(b0),"r"(b1))

__device__ __forceinline__ uint32_t smem_u32(const void* p) {
    uint32_t a;
    asm("{ .reg .u64 t; cvta.to.shared.u64 t, %1; cvt.u32.u64 %0, t; }" : "=r"(a) : "l"(p));
    return a;
}
__device__ __forceinline__ void bulkld(uint32_t sdst, const void* gsrc, uint32_t mbar, uint32_t bytes) {
    asm volatile("cp.async.bulk.shared::cluster.global.mbarrier::complete_tx::bytes [%0], [%1], %2, [%3];"
        :: "r"(sdst), "l"(gsrc), "r"(bytes), "r"(mbar) : "memory");
}
#define MB_INIT(mb, c)    asm volatile("mbarrier.init.shared.b64 [%0], %1;" :: "r"(mb), "r"(c) : "memory")
#define MB_EXPECT(mb, nb) asm volatile("mbarrier.arrive.expect_tx.shared.b64 _, [%0], %1;" :: "r"(mb), "r"(nb) : "memory")
#define MB_WAIT(mb, par) do { \
    asm volatile("{\n\t.reg .pred P1;\n\tWL_%=:\n\t" \
        "mbarrier.try_wait.parity.acquire.cta.shared::cta.b64 P1, [%0], %1, 0x989680;\n\t" \
        "@P1 bra.uni WD_%=;\n\tbra.uni WL_%=;\n\tWD_%=:\n\t}" \
        :: "r"(mb), "r"(par) : "memory"); } while (0)

// ============================================================================
// proj3: token-per-lane compute (bit-identical order to R13), head-sequential
// smem staging, fully coalesced global stores. grid (256, 3), 128 threads.
// smem layout (floats): xT[256*33] | xsT[32*33] | ystage[256*33] | sstage[32*33]
// ============================================================================
#define P3_XT   0
#define P3_XST  8448
#define P3_YS   9504
#define P3_SS   17952
#define P3_SMEM ((17952 + 1056) * 4)

__global__ void proj3_kernel(
    const float* __restrict__ mv_q,  const float* __restrict__ s_q,
    const float* __restrict__ mv_kv, const float* __restrict__ s_kv,
    const float* __restrict__ wq_mv, const float* __restrict__ wq_s2mv,
    const float* __restrict__ wq_m2s, const float* __restrict__ wq_s2s,
    const float* __restrict__ bq_mv, const float* __restrict__ bq_s,
    const float* __restrict__ wk_mv, const float* __restrict__ wk_s2mv,
    const float* __restrict__ wk_m2s, const float* __restrict__ wk_s2s,
    const float* __restrict__ bk_mv, const float* __restrict__ bk_s,
    const float* __restrict__ wv_mv, const float* __restrict__ wv_s2mv,
    const float* __restrict__ wv_m2s, const float* __restrict__ wv_s2s,
    const float* __restrict__ bv_mv, const float* __restrict__ bv_s)
{
    extern __shared__ float psm[];
    float* xT     = psm + P3_XT;
    float* xsT    = psm + P3_XST;
    float* ystage = psm + P3_YS;
    float* sstage = psm + P3_SS;

    const int sel = blockIdx.y;
    const int ntok = (sel == 0) ? NQ_ : NKV_;
    const int ntiles = (B_ * ntok) / 32;
    const int tile = blockIdx.x;
    if (tile >= ntiles) return;

    const float* x_mv = (sel == 0) ? mv_q : mv_kv;
    const float* x_s  = (sel == 0) ? s_q  : s_kv;
    const float* w_mv    = (sel == 0) ? wq_mv  : (sel == 1) ? wk_mv  : wv_mv;
    const float* w_s2mv  = (sel == 0) ? wq_s2mv: (sel == 1) ? wk_s2mv: wv_s2mv;
    const float* w_mvs2s = (sel == 0) ? wq_m2s : (sel == 1) ? wk_m2s : wv_m2s;
    const float* w_s2s   = (sel == 0) ? wq_s2s : (sel == 1) ? wk_s2s : wv_s2s;
    const float* b_mv    = (sel == 0) ? bq_mv  : (sel == 1) ? bk_mv  : bv_mv;
    const float* b_s     = (sel == 0) ? bq_s   : (sel == 1) ? bk_s   : bv_s;
    float* out = (sel == 0) ? QB : (sel == 1) ? KB : VB;
    const int applyMetric = (sel == 1);

    const int tid = threadIdx.x, w = tid >> 5, lane = tid & 31;
    const int t0 = tile * 32;
    const int b = t0 / ntok, n0 = t0 % ntok;

    // stage x (coalesced read, transposed write)
    {
        const float4* src = (const float4*)(x_mv + (size_t)t0 * 256);
#pragma unroll
        for (int i = 0; i < 16; ++i) {
            int f4 = i * 128 + tid;
            int tok = f4 >> 6, feat4 = f4 & 63;
            float4 v = src[f4];
            xT[(feat4 * 4 + 0) * 33 + tok] = v.x;
            xT[(feat4 * 4 + 1) * 33 + tok] = v.y;
            xT[(feat4 * 4 + 2) * 33 + tok] = v.z;
            xT[(feat4 * 4 + 3) * 33 + tok] = v.w;
        }
        const float* ssrc = x_s + (size_t)t0 * 32;
#pragma unroll
        for (int i = 0; i < 8; ++i) {
            int idx = i * 128 + tid;
            int tok = idx >> 5, s = idx & 31;
            xsT[s * 33 + tok] = ssrc[tok * 32 + s];
        }
    }
    __syncthreads();

    for (int h = 0; h < 8; ++h) {
        // mv channels of head h: hid = w*4 + j, o = h + 8*hid (warp-uniform weights)
#pragma unroll
        for (int j = 0; j < 4; ++j) {
            const int hid = w * 4 + j, o = h + 8 * hid;
            const float* wr = w_mv + o * 80;
            float a0 = b_mv[o];
            const float* ws = w_s2mv + o * 32;
#pragma unroll
            for (int s = 0; s < 32; ++s) a0 += xsT[s * 33 + lane] * ws[s];
#pragma unroll
            for (int x = 0; x < 16; ++x) {
                float acc = (x == 0) ? a0 : 0.f;
                const int g = GRADEA[x];
#pragma unroll
                for (int i = 0; i < 16; ++i)
                    acc += xT[(i * 16 + x) * 33 + lane] * wr[i * 5 + g];
                if (applyMetric) acc *= METRICA[x];
                ystage[(hid * 16 + x) * 33 + lane] = acc;
            }
        }
        // scalar channels of head h: sid = w*8 + j2, o = h + 8*sid
#pragma unroll
        for (int j2 = 0; j2 < 8; ++j2) {
            const int sid = w * 8 + j2, o = h + 8 * sid;
            float y = b_s[o];
            const float* wm = w_mvs2s + o * 16;
#pragma unroll
            for (int i = 0; i < 16; ++i) y += xT[(i * 16) * 33 + lane] * wm[i];
            const float* ws2 = w_s2s + o * 32;
#pragma unroll
            for (int s = 0; s < 32; ++s) y += xsT[s * 33 + lane] * ws2[s];
            sstage[sid * 33 + lane] = y;
        }
        __syncthreads();

        // coalesced writes for head h
        float* rowb = out + ((size_t)(b * 8 + h) * ntok + n0) * D_;
#pragma unroll
        for (int i = 0; i < 64; ++i) {
            int e = i * 128 + tid, tok = e >> 8, feat = e & 255;
            rowb[(size_t)tok * D_ + feat] = ystage[feat * 33 + tok];
        }
#pragma unroll
        for (int i = 0; i < 8; ++i) {
            int e = i * 128 + tid, tok = e >> 5, sid2 = e & 31;
            rowb[(size_t)tok * D_ + 256 + sid2] = sstage[sid2 * 33 + tok];
        }
        __syncthreads();
    }
}

// ============================================================================
// repackQ: grid (8, 32), 256 thr (unchanged from R13).
// ============================================================================
#define STGS 292
__global__ void repackQ_kernel()
{
    extern __shared__ float ss[];
    const int qt = blockIdx.x, bh = blockIdx.y, tid = threadIdx.x;
    const float SCALE = 0.0589255650988789f;
    const float* src = QB + ((size_t)bh * NQ_ + qt * 128) * D_;
#pragma unroll
    for (int i = 0; i < 36; ++i) {
        int idx = i * 256 + tid, row = idx / 72, c4 = idx % 72;
        float4 v = *(const float4*)(src + (size_t)row * D_ + c4 * 4);
        float* d = ss + row * STGS + c4 * 4;
        d[0] = v.x; d[1] = v.y; d[2] = v.z; d[3] = v.w;
    }
    __syncthreads();
    uint32_t* dst = QFG + (size_t)(bh * 8 + qt) * 36864;
#pragma unroll
    for (int i = 0; i < 18; ++i) {
        int gidx = i * 256 + tid;
        int ms = gidx / 576, rem = gidx % 576, ks = rem >> 5, lane = rem & 31;
        int g = lane >> 2, t = lane & 3;
        int r0 = ms * 16 + g, c0 = ks * 16 + 2 * t;
        float v[8];
        v[0] = ss[r0 * STGS + c0] * SCALE;        v[1] = ss[r0 * STGS + c0 + 1] * SCALE;
        v[2] = ss[(r0+8) * STGS + c0] * SCALE;    v[3] = ss[(r0+8) * STGS + c0 + 1] * SCALE;
        v[4] = ss[r0 * STGS + c0 + 8] * SCALE;    v[5] = ss[r0 * STGS + c0 + 9] * SCALE;
        v[6] = ss[(r0+8) * STGS + c0 + 8] * SCALE;v[7] = ss[(r0+8) * STGS + c0 + 9] * SCALE;
        uint4 hi = { pk2b(v[0],v[1]), pk2b(v[2],v[3]), pk2b(v[4],v[5]), pk2b(v[6],v[7]) };
        uint4 lo = { pk2b(bf16res(v[0]),bf16res(v[1])), pk2b(bf16res(v[2]),bf16res(v[3])),
                     pk2b(bf16res(v[4]),bf16res(v[5])), pk2b(bf16res(v[6]),bf16res(v[7])) };
        *(uint4*)(dst + (size_t)gidx * 4)          = hi;
        *(uint4*)(dst + 18432 + (size_t)gidx * 4)  = lo;
    }
}

// ============================================================================
// repackKV: K hi+lo; V hi+lo. grid (32, 32, 2), 256 thr (unchanged).
// ============================================================================
__global__ void repackKV_kernel()
{
    extern __shared__ float ss[];
    const int kt = blockIdx.x, bh = blockIdx.y, zv = blockIdx.z, tid = threadIdx.x;
    const float* src = (zv ? VB : KB) + ((size_t)bh * NKV_ + kt * 64) * D_;
#pragma unroll
    for (int i = 0; i < 18; ++i) {
        int idx = i * 256 + tid, row = idx / 72, c4 = idx % 72;
        float4 v = *(const float4*)(src + (size_t)row * D_ + c4 * 4);
        float* d = ss + row * STGS + c4 * 4;
        d[0] = v.x; d[1] = v.y; d[2] = v.z; d[3] = v.w;
    }
    __syncthreads();
    uint32_t* dst = (zv ? VFG : KFG) + (size_t)(bh * 32 + kt) * 3 * 6144;
    if (!zv) {
#pragma unroll
        for (int i = 0; i < 18; ++i) {
            int e = i * 256 + tid;
            int c = e / 1536, rem = e % 1536;
            int n = rem / 192, rem2 = rem % 192, ksl = rem2 >> 5, lane = rem2 & 31;
            int g = lane >> 2, t = lane & 3;
            int key = n * 8 + g, d0 = c * 96 + ksl * 16 + 2 * t;
            float x0 = ss[key * STGS + d0],     x1 = ss[key * STGS + d0 + 1];
            float x2 = ss[key * STGS + d0 + 8], x3 = ss[key * STGS + d0 + 9];
            uint32_t* ch = dst + (size_t)c * 6144;
            int go = ((n * 6 + ksl) * 32 + lane) * 2;
            *(uint2*)(ch + go)        = make_uint2(pk2b(x0, x1), pk2b(x2, x3));
            *(uint2*)(ch + 3072 + go) = make_uint2(pk2b(bf16res(x0), bf16res(x1)),
                                                   pk2b(bf16res(x2), bf16res(x3)));
        }
    } else {
#pragma unroll
        for (int i = 0; i < 18; ++i) {
            int e = i * 256 + tid;
            int c = e / 1536, rem = e % 1536;
            int ntl = rem / 128, rem2 = rem % 128, ks = rem2 >> 5, lane = rem2 & 31;
            int g = lane >> 2, t = lane & 3;
            int key0 = ks * 16 + 2 * t, d = c * 96 + ntl * 8 + g;
            float x0 = ss[key0 * STGS + d],       x1 = ss[(key0+1) * STGS + d];
            float x2 = ss[(key0+8) * STGS + d],   x3 = ss[(key0+9) * STGS + d];
            uint32_t* ch = dst + (size_t)c * 6144;
            int go = ((ntl * 4 + ks) * 32 + lane) * 2;
            *(uint2*)(ch + go)        = make_uint2(pk2b(x0, x1), pk2b(x2, x3));
            *(uint2*)(ch + 3072 + go) = make_uint2(pk2b(bf16res(x0), bf16res(x1)),
                                                   pk2b(bf16res(x2), bf16res(x3)));
        }
    }
}

// ============================================================================
// attn8: register-resident FA2, split-bf16 — unchanged (R10/R13 config).
// ============================================================================
#define SM_BYTES (147456 + 3 * 24576 + 64)

__global__ __launch_bounds__(256, 1) void attn8_kernel()
{
    extern __shared__ uint32_t smu[];
    uint32_t* Qh = smu;
    uint32_t* Ql = smu + 18432;
    uint32_t* bufs[3] = { smu + 36864, smu + 43008, smu + 49152 };

    const int tid = threadIdx.x, bh = blockIdx.y, qt = blockIdx.x;
    const int w = tid >> 5, lane = tid & 31, g = lane >> 2, t = lane & 3;

    const uint32_t sb = smem_u32(smu);
    const uint32_t mbase = sb + (36864 + 3 * 6144) * 4;
    const uint32_t mbQ = mbase + 24;

    const uint32_t* KFb = KFG + (size_t)(bh * 32) * 3 * 6144;
    const uint32_t* VFb = VFG + (size_t)(bh * 32) * 3 * 6144;

    if (tid == 0) {
        MB_INIT(mbase + 0, 1); MB_INIT(mbase + 8, 1); MB_INIT(mbase + 16, 1);
        MB_INIT(mbQ, 1);
    }
    __syncthreads();
    if (tid == 0) {
        MB_EXPECT(mbQ, 147456u);
        bulkld(sb, QFG + (size_t)(bh * 8 + qt) * 36864, mbQ, 147456u);
#pragma unroll
        for (int c = 0; c < 3; ++c) {
            MB_EXPECT(mbase + 8 * c, 24576u);
            bulkld(sb + (36864 + c * 6144) * 4, KFb + c * 6144, mbase + 8 * c, 24576u);
        }
    }

    float O[3][12][4];
#pragma unroll
    for (int c = 0; c < 3; ++c)
#pragma unroll
        for (int n = 0; n < 12; ++n)
#pragma unroll
            for (int k = 0; k < 4; ++k) O[c][n][k] = 0.f;
    float mA = -1e30f, mB = -1e30f, lA = 0.f, lB = 0.f;

    MB_WAIT(mbQ, 0);

    for (int kt = 0; kt < 32; ++kt) {
        const uint32_t* VFt = VFb + (size_t)kt * 3 * 6144;
        const uint32_t* KFn = KFb + (size_t)(kt + 1) * 3 * 6144;

        float cS[8][4];
#pragma unroll
        for (int n = 0; n < 8; ++n)
#pragma unroll
            for (int k = 0; k < 4; ++k) cS[n][k] = 0.f;

#pragma unroll
        for (int c = 0; c < 3; ++c) {
            MB_WAIT(mbase + 8 * c, 0);
            const uint32_t* buf = bufs[c];
#pragma unroll
            for (int ksl = 0; ksl < 6; ++ksl) {
                const int ksg = c * 6 + ksl;
                uint4 Ah = *(const uint4*)(Qh + ((w * 18 + ksg) * 32 + lane) * 4);
                uint4 Al = *(const uint4*)(Ql + ((w * 18 + ksg) * 32 + lane) * 4);
#pragma unroll
                for (int n = 0; n < 8; ++n) {
                    uint2 bh2 = *(const uint2*)(buf + ((n * 6 + ksl) * 32 + lane) * 2);
                    uint2 bl2 = *(const uint2*)(buf + 3072 + ((n * 6 + ksl) * 32 + lane) * 2);
                    MMA16(cS[n], Ah.x, Ah.y, Ah.z, Ah.w, bh2.x, bh2.y);
                    MMA16(cS[n], Al.x, Al.y, Al.z, Al.w, bh2.x, bh2.y);
                    MMA16(cS[n], Ah.x, Ah.y, Ah.z, Ah.w, bl2.x, bl2.y);
                }
            }
            __syncthreads();
            if (tid == 0) {
                MB_EXPECT(mbase + 8 * c, 24576u);
                bulkld(sb + (36864 + c * 6144) * 4, VFt + c * 6144, mbase + 8 * c, 24576u);
            }
        }

        float mxA = -1e30f, mxB = -1e30f;
#pragma unroll
        for (int n = 0; n < 8; ++n) {
            mxA = fmaxf(mxA, fmaxf(cS[n][0], cS[n][1]));
            mxB = fmaxf(mxB, fmaxf(cS[n][2], cS[n][3]));
        }
        mxA = fmaxf(mxA, __shfl_xor_sync(0xffffffffu, mxA, 1));
        mxA = fmaxf(mxA, __shfl_xor_sync(0xffffffffu, mxA, 2));
        mxB = fmaxf(mxB, __shfl_xor_sync(0xffffffffu, mxB, 1));
        mxB = fmaxf(mxB, __shfl_xor_sync(0xffffffffu, mxB, 2));
        const float mnA = fmaxf(mA, mxA), mnB = fmaxf(mB, mxB);
        const float alA = __expf(mA - mnA), alB = __expf(mB - mnB);
        mA = mnA; mB = mnB;

        uint32_t PhT[8], PhB[8], PlT[8], PlB[8];
        float sA = 0.f, sB = 0.f;
#pragma unroll
        for (int n = 0; n < 8; ++n) {
            float e0 = __expf(cS[n][0] - mnA), e1 = __expf(cS[n][1] - mnA);
            float e2 = __expf(cS[n][2] - mnB), e3 = __expf(cS[n][3] - mnB);
            sA += e0 + e1; sB += e2 + e3;
            PhT[n] = pk2b(e0, e1); PhB[n] = pk2b(e2, e3);
            PlT[n] = pk2b(bf16res(e0), bf16res(e1));
            PlB[n] = pk2b(bf16res(e2), bf16res(e3));
        }
        sA += __shfl_xor_sync(0xffffffffu, sA, 1);
        sA += __shfl_xor_sync(0xffffffffu, sA, 2);
        sB += __shfl_xor_sync(0xffffffffu, sB, 1);
        sB += __shfl_xor_sync(0xffffffffu, sB, 2);
        lA = lA * alA + sA;
        lB = lB * alB + sB;
#pragma unroll
        for (int c = 0; c < 3; ++c)
#pragma unroll
            for (int n = 0; n < 12; ++n) {
                O[c][n][0] *= alA; O[c][n][1] *= alA;
                O[c][n][2] *= alB; O[c][n][3] *= alB;
            }

#pragma unroll
        for (int c = 0; c < 3; ++c) {
            MB_WAIT(mbase + 8 * c, 1);
            const uint32_t* buf = bufs[c];
#pragma unroll
            for (int ks = 0; ks < 4; ++ks) {
                uint32_t ah0 = PhT[2*ks], ah1 = PhB[2*ks], ah2 = PhT[2*ks+1], ah3 = PhB[2*ks+1];
                uint32_t al0 = PlT[2*ks], al1 = PlB[2*ks], al2 = PlT[2*ks+1], al3 = PlB[2*ks+1];
#pragma unroll
                for (int ntl = 0; ntl < 12; ++ntl) {
                    uint2 vh = *(const uint2*)(buf + ((ntl * 4 + ks) * 32 + lane) * 2);
                    uint2 vl = *(const uint2*)(buf + 3072 + ((ntl * 4 + ks) * 32 + lane) * 2);
                    MMA16(O[c][ntl], ah0, ah1, ah2, ah3, vh.x, vh.y);
                    MMA16(O[c][ntl], al0, al1, al2, al3, vh.x, vh.y);
                    MMA16(O[c][ntl], ah0, ah1, ah2, ah3, vl.x, vl.y);
                }
            }
            __syncthreads();
            if (kt < 31 && tid == 0) {
                MB_EXPECT(mbase + 8 * c, 24576u);
                bulkld(sb + (36864 + c * 6144) * 4, KFn + c * 6144, mbase + 8 * c, 24576u);
            }
        }
    }

    const float liA = 1.f / lA, liB = 1.f / lB;
    const int b = bh >> 3, hh = bh & 7;
    const int rA = qt * 128 + w * 16 + g, rB = rA + 8;
    float* oA = OB + (((size_t)(b * NQ_ + rA)) * 8 + hh) * D_;
    float* oB = OB + (((size_t)(b * NQ_ + rB)) * 8 + hh) * D_;
#pragma unroll
    for (int c = 0; c < 3; ++c)
#pragma unroll
        for (int n = 0; n < 12; ++n) {
            int d = c * 96 + n * 8 + 2 * t;
            *(float2*)(oA + d) = make_float2(O[c][n][0] * liA, O[c][n][1] * liA);
            *(float2*)(oB + d) = make_float2(O[c][n][2] * liB, O[c][n][3] * liB);
        }
}

// ============================================================================
// outproj2 (exact R13 version): 8-token tiles, 256 threads. grid = 512.
// ============================================================================
#define OP_SMEM (2304 * 9 * 4 + 128 * 4)

__global__ void outproj2_kernel(const float* __restrict__ wo_mv, const float* __restrict__ wo_s2mv,
                                const float* __restrict__ wo_mvs2s, const float* __restrict__ wo_s2s,
                                const float* __restrict__ bo_mv, const float* __restrict__ bo_s,
                                float* __restrict__ d_out)
{
    extern __shared__ float xT[];           // [2304][9]
    float* a0sm = xT + 2304 * 9;            // [tok8][o16]
    const int blk = blockIdx.x, tid = threadIdx.x;

    {
        const float4* src = (const float4*)(OB + (size_t)blk * 8 * 2304);
#pragma unroll
        for (int i = 0; i < 18; ++i) {
            int idx = i * 256 + tid;
            int tok = idx / 576, f4 = idx % 576;
            float4 v = src[(size_t)tok * 576 + f4];
            xT[(f4 * 4 + 0) * 9 + tok] = v.x;
            xT[(f4 * 4 + 1) * 9 + tok] = v.y;
            xT[(f4 * 4 + 2) * 9 + tok] = v.z;
            xT[(f4 * 4 + 3) * 9 + tok] = v.w;
        }
    }
    __syncthreads();

    {
        const int tok = tid >> 5, o = (tid >> 1) & 15, part = tid & 1;
        float a = 0.f;
        const float* ws = wo_s2mv + o * 256 + part * 128;
#pragma unroll
        for (int s = 0; s < 128; ++s) {
            int s2 = part * 128 + s;
            int feat = (s2 >> 5) * 288 + 256 + (s2 & 31);
            a += xT[feat * 9 + tok] * ws[s];
        }
        a += __shfl_xor_sync(0xffffffffu, a, 1);
        if (part == 0) a0sm[tok * 16 + o] = a + bo_mv[o];
    }
    __syncthreads();

    const int og = tid >> 3, tok = tid & 7;
    const int tglob = blk * 8 + tok;

#pragma unroll
    for (int j = 0; j < 8; ++j) {
        const int outIdx = j * 32 + og;
        const int o = outIdx >> 4, x = outIdx & 15;
        const int gg = GRADE_RT[x];
        const float* wp = wo_mv + (size_t)o * 640 + gg;
        float y = (x == 0) ? a0sm[tok * 16 + o] : 0.f;
#pragma unroll 16
        for (int i = 0; i < 128; ++i) {
            int feat = (i >> 4) * 288 + (i & 15) * 16 + x;
            y += xT[feat * 9 + tok] * wp[i * 5];
        }
        d_out[(size_t)tglob * 256 + outIdx] = y;
    }
    {
        const int s = og;
        float y = bo_s[s];
        const float* wm = wo_mvs2s + s * 128;
#pragma unroll 16
        for (int i = 0; i < 128; ++i) {
            int feat = (i >> 4) * 288 + (i & 15) * 16;
            y += xT[feat * 9 + tok] * wm[i];
        }
        const float* ws = wo_s2s + s * 256;
#pragma unroll 16
        for (int s2 = 0; s2 < 256; ++s2) {
            int feat = (s2 >> 5) * 288 + 256 + (s2 & 31);
            y += xT[feat * 9 + tok] * ws[s2];
        }
        d_out[(size_t)B_ * NQ_ * 256 + (size_t)tglob * 32 + s] = y;
    }
}

extern "C" void kernel_launch(void* const* d_in, const int* in_sizes, int n_in,
                              void* d_out, int out_size)
{
    (void)in_sizes; (void)n_in; (void)out_size;
    const float* mv_kv = (const float*)d_in[0];
    const float* mv_q  = (const float*)d_in[1];
    const float* s_kv  = (const float*)d_in[2];
    const float* s_q   = (const float*)d_in[3];
    const float* wq_mv = (const float*)d_in[4],  *wq_s2mv = (const float*)d_in[5];
    const float* wq_m2s = (const float*)d_in[6], *wq_s2s = (const float*)d_in[7];
    const float* bq_mv = (const float*)d_in[8],  *bq_s = (const float*)d_in[9];
    const float* wk_mv = (const float*)d_in[10], *wk_s2mv = (const float*)d_in[11];
    const float* wk_m2s = (const float*)d_in[12],*wk_s2s = (const float*)d_in[13];
    const float* bk_mv = (const float*)d_in[14], *bk_s = (const float*)d_in[15];
    const float* wv_mv = (const float*)d_in[16], *wv_s2mv = (const float*)d_in[17];
    const float* wv_m2s = (const float*)d_in[18],*wv_s2s = (const float*)d_in[19];
    const float* bv_mv = (const float*)d_in[20], *bv_s = (const float*)d_in[21];
    const float* wo_mv = (const float*)d_in[22], *wo_s2mv = (const float*)d_in[23];
    const float* wo_m2s = (const float*)d_in[24],*wo_s2s = (const float*)d_in[25];
    const float* bo_mv = (const float*)d_in[26], *bo_s = (const float*)d_in[27];

    const int stageQ = 128 * STGS * sizeof(float);
    const int stageKV = 64 * STGS * sizeof(float);
    cudaFuncSetAttribute(proj3_kernel, cudaFuncAttributeMaxDynamicSharedMemorySize, P3_SMEM);
    cudaFuncSetAttribute(repackQ_kernel, cudaFuncAttributeMaxDynamicSharedMemorySize, stageQ);
    cudaFuncSetAttribute(repackKV_kernel, cudaFuncAttributeMaxDynamicSharedMemorySize, stageKV);
    cudaFuncSetAttribute(attn8_kernel, cudaFuncAttributeMaxDynamicSharedMemorySize, SM_BYTES);
    cudaFuncSetAttribute(outproj2_kernel, cudaFuncAttributeMaxDynamicSharedMemorySize, OP_SMEM);

    proj3_kernel<<<dim3(256, 3), 128, P3_SMEM>>>(
        mv_q, s_q, mv_kv, s_kv,
        wq_mv, wq_s2mv, wq_m2s, wq_s2s, bq_mv, bq_s,
        wk_mv, wk_s2mv, wk_m2s, wk_s2s, bk_mv, bk_s,
        wv_mv, wv_s2mv, wv_m2s, wv_s2s, bv_mv, bv_s);
    repackQ_kernel<<<dim3(8, 32), 256, stageQ>>>();
    repackKV_kernel<<<dim3(32, 32, 2), 256, stageKV>>>();
    attn8_kernel<<<dim3(8, 32), 256, SM_BYTES>>>();
    outproj2_kernel<<<512, 256, OP_SMEM>>>(wo_mv, wo_s2mv, wo_m2s, wo_s2s, bo_mv, bo_s,
                                           (float*)d_out);
}

// round 17
// speedup vs baseline: 1.3815x; 1.0526x over previous
#include <cuda_runtime.h>
#include <cuda_bf16.h>
#include <math.h>
#include <stdint.h>

#define B_    4
#define NQ_   1024
#define NKV_  2048
#define D_    288

__device__ constexpr int   GRADEA[16] = {0,1,1,1,1,2,2,2,2,2,2,3,3,3,3,4};
__device__ constexpr float METRICA[16] = {1.f,1.f,-1.f,-1.f,-1.f,-1.f,-1.f,-1.f,
                                          1.f,1.f, 1.f, 1.f, 1.f, 1.f,-1.f,-1.f};
__constant__ int GRADE_RT[16] = {0,1,1,1,1,2,2,2,2,2,2,3,3,3,3,4};

// scratch
__device__ __align__(1024) float OB[(size_t)B_*NQ_*8*D_];
// packed bf16x2 fragment images
__device__ __align__(1024) uint32_t QFG[(size_t)32*8*36864];
__device__ __align__(1024) uint32_t KFG[(size_t)32*32*3*6144];
__device__ __align__(1024) uint32_t VFG[(size_t)32*32*3*6144];

__device__ __forceinline__ uint32_t pk2b(float lo, float hi) {
    __nv_bfloat162 h = __floats2bfloat162_rn(lo, hi);
    return *(uint32_t*)&h;
}
__device__ __forceinline__ float bf16res(float x) {
    return x - __bfloat162float(__float2bfloat16_rn(x));
}
#define MMA16(c,a0,a1,a2,a3,b0,b1) \
    asm volatile("mma.sync.aligned.m16n8k16.row.col.f32.bf16.bf16.f32 " \
        "{%0,%1,%2,%3},{%4,%5,%6,%7},{%8,%9},{%0,%1,%2,%3};" \
        : "+f"((c)[0]),"+f"((c)[1]),"+f"((c)[2]),"+f"((c)[3]) \
        : "r"(a0),"r"(a1),"r"(a2),"r"(a3),"r"(b0),"r"(b1))

__device__ __forceinline__ uint32_t smem_u32(const void* p) {
    uint32_t a;
    asm("{ .reg .u64 t; cvta.to.shared.u64 t, %1; cvt.u32.u64 %0, t; }" : "=r"(a) : "l"(p));
    return a;
}
__device__ __forceinline__ void bulkld(uint32_t sdst, const void* gsrc, uint32_t mbar, uint32_t bytes) {
    asm volatile("cp.async.bulk.shared::cluster.global.mbarrier::complete_tx::bytes [%0], [%1], %2, [%3];"
        :: "r"(sdst), "l"(gsrc), "r"(bytes), "r"(mbar) : "memory");
}
#define MB_INIT(mb, c)    asm volatile("mbarrier.init.shared.b64 [%0], %1;" :: "r"(mb), "r"(c) : "memory")
#define MB_EXPECT(mb, nb) asm volatile("mbarrier.arrive.expect_tx.shared.b64 _, [%0], %1;" :: "r"(mb), "r"(nb) : "memory")
#define MB_WAIT(mb, par) do { \
    asm volatile("{\n\t.reg .pred P1;\n\tWL_%=:\n\t" \
        "mbarrier.try_wait.parity.acquire.cta.shared::cta.b64 P1, [%0], %1, 0x989680;\n\t" \
        "@P1 bra.uni WD_%=;\n\tbra.uni WL_%=;\n\tWD_%=:\n\t}" \
        :: "r"(mb), "r"(par) : "memory"); } while (0)

// ============================================================================
// proj4: proj3 compute (bit-identical accumulation order) + FUSED fragment
// emission. No QB/KB/VB round-trip. grid (256, 3), 128 threads.
// smem (floats): xT[256*33] | xsT[32*33] | ystage[256*33] | sstage[32*33]
// ============================================================================
#define P4_XT   0
#define P4_XST  8448
#define P4_YS   9504
#define P4_SS   17952
#define P4_SMEM ((17952 + 1056) * 4)

__device__ __forceinline__ float getf(const float* ystage, const float* sstage, int f, int tok) {
    return (f < 256) ? ystage[f * 33 + tok] : sstage[(f - 256) * 33 + tok];
}

__global__ void proj4_kernel(
    const float* __restrict__ mv_q,  const float* __restrict__ s_q,
    const float* __restrict__ mv_kv, const float* __restrict__ s_kv,
    const float* __restrict__ wq_mv, const float* __restrict__ wq_s2mv,
    const float* __restrict__ wq_m2s, const float* __restrict__ wq_s2s,
    const float* __restrict__ bq_mv, const float* __restrict__ bq_s,
    const float* __restrict__ wk_mv, const float* __restrict__ wk_s2mv,
    const float* __restrict__ wk_m2s, const float* __restrict__ wk_s2s,
    const float* __restrict__ bk_mv, const float* __restrict__ bk_s,
    const float* __restrict__ wv_mv, const float* __restrict__ wv_s2mv,
    const float* __restrict__ wv_m2s, const float* __restrict__ wv_s2s,
    const float* __restrict__ bv_mv, const float* __restrict__ bv_s)
{
    extern __shared__ float psm[];
    float* xT     = psm + P4_XT;
    float* xsT    = psm + P4_XST;
    float* ystage = psm + P4_YS;
    float* sstage = psm + P4_SS;

    const int sel = blockIdx.y;
    const int ntok = (sel == 0) ? NQ_ : NKV_;
    const int ntiles = (B_ * ntok) / 32;
    const int tile = blockIdx.x;
    if (tile >= ntiles) return;

    const float* x_mv = (sel == 0) ? mv_q : mv_kv;
    const float* x_s  = (sel == 0) ? s_q  : s_kv;
    const float* w_mv    = (sel == 0) ? wq_mv  : (sel == 1) ? wk_mv  : wv_mv;
    const float* w_s2mv  = (sel == 0) ? wq_s2mv: (sel == 1) ? wk_s2mv: wv_s2mv;
    const float* w_mvs2s = (sel == 0) ? wq_m2s : (sel == 1) ? wk_m2s : wv_m2s;
    const float* w_s2s   = (sel == 0) ? wq_s2s : (sel == 1) ? wk_s2s : wv_s2s;
    const float* b_mv    = (sel == 0) ? bq_mv  : (sel == 1) ? bk_mv  : bv_mv;
    const float* b_s     = (sel == 0) ? bq_s   : (sel == 1) ? bk_s   : bv_s;
    const int applyMetric = (sel == 1);
    const float SCALE = 0.0589255650988789f;   // folded into Q fragments

    const int tid = threadIdx.x, w = tid >> 5, lane = tid & 31;
    const int t0 = tile * 32;
    const int b = t0 / ntok, n0 = t0 % ntok;

    // stage x (coalesced read, transposed write)
    {
        const float4* src = (const float4*)(x_mv + (size_t)t0 * 256);
#pragma unroll
        for (int i = 0; i < 16; ++i) {
            int f4 = i * 128 + tid;
            int tok = f4 >> 6, feat4 = f4 & 63;
            float4 v = src[f4];
            xT[(feat4 * 4 + 0) * 33 + tok] = v.x;
            xT[(feat4 * 4 + 1) * 33 + tok] = v.y;
            xT[(feat4 * 4 + 2) * 33 + tok] = v.z;
            xT[(feat4 * 4 + 3) * 33 + tok] = v.w;
        }
        const float* ssrc = x_s + (size_t)t0 * 32;
#pragma unroll
        for (int i = 0; i < 8; ++i) {
            int idx = i * 128 + tid;
            int tok = idx >> 5, s = idx & 31;
            xsT[s * 33 + tok] = ssrc[tok * 32 + s];
        }
    }
    __syncthreads();

    for (int h = 0; h < 8; ++h) {
        // ---- compute head h into ystage/sstage (identical to proj3) ----
#pragma unroll
        for (int j = 0; j < 4; ++j) {
            const int hid = w * 4 + j, o = h + 8 * hid;
            const float* wr = w_mv + o * 80;
            float a0 = b_mv[o];
            const float* ws = w_s2mv + o * 32;
#pragma unroll
            for (int s = 0; s < 32; ++s) a0 += xsT[s * 33 + lane] * ws[s];
#pragma unroll
            for (int x = 0; x < 16; ++x) {
                float acc = (x == 0) ? a0 : 0.f;
                const int g = GRADEA[x];
#pragma unroll
                for (int i = 0; i < 16; ++i)
                    acc += xT[(i * 16 + x) * 33 + lane] * wr[i * 5 + g];
                if (applyMetric) acc *= METRICA[x];
                ystage[(hid * 16 + x) * 33 + lane] = acc;
            }
        }
#pragma unroll
        for (int j2 = 0; j2 < 8; ++j2) {
            const int sid = w * 8 + j2, o = h + 8 * sid;
            float y = b_s[o];
            const float* wm = w_mvs2s + o * 16;
#pragma unroll
            for (int i = 0; i < 16; ++i) y += xT[(i * 16) * 33 + lane] * wm[i];
            const float* ws2 = w_s2s + o * 32;
#pragma unroll
            for (int s = 0; s < 32; ++s) y += xsT[s * 33 + lane] * ws2[s];
            sstage[sid * 33 + lane] = y;
        }
        __syncthreads();

        // ---- fused fragment emission for head h ----
        const int bh = b * 8 + h;
        if (sel == 0) {
            // Q A-frags: rows n0..n0+31 => qt = n0/128, ms = ms0 + {0,1}
            uint32_t* dst = QFG + (size_t)(bh * 8 + (n0 >> 7)) * 36864;
            const int ms0 = (n0 & 127) >> 4;
#pragma unroll
            for (int i = 0; i < 9; ++i) {
                int e = i * 128 + tid;               // 0..1151
                int msr = e / 576, rem = e % 576, ks = rem >> 5, ln = rem & 31;
                int g = ln >> 2, t = ln & 3;
                int tokA = msr * 16 + g, tokB = tokA + 8;
                int c0 = ks * 16 + 2 * t;
                float v0 = getf(ystage, sstage, c0,     tokA) * SCALE;
                float v1 = getf(ystage, sstage, c0 + 1, tokA) * SCALE;
                float v2 = getf(ystage, sstage, c0,     tokB) * SCALE;
                float v3 = getf(ystage, sstage, c0 + 1, tokB) * SCALE;
                float v4 = getf(ystage, sstage, c0 + 8, tokA) * SCALE;
                float v5 = getf(ystage, sstage, c0 + 9, tokA) * SCALE;
                float v6 = getf(ystage, sstage, c0 + 8, tokB) * SCALE;
                float v7 = getf(ystage, sstage, c0 + 9, tokB) * SCALE;
                int gidx = (ms0 + msr) * 576 + ks * 32 + ln;
                uint4 hi = { pk2b(v0,v1), pk2b(v2,v3), pk2b(v4,v5), pk2b(v6,v7) };
                uint4 lo = { pk2b(bf16res(v0),bf16res(v1)), pk2b(bf16res(v2),bf16res(v3)),
                             pk2b(bf16res(v4),bf16res(v5)), pk2b(bf16res(v6),bf16res(v7)) };
                *(uint4*)(dst + (size_t)gidx * 4)         = hi;
                *(uint4*)(dst + 18432 + (size_t)gidx * 4) = lo;
            }
        } else if (sel == 1) {
            // K B-frags: keys n0..n0+31 => ktile = n0/64, n = half*4 + {0..3}
            uint32_t* dst = KFG + (size_t)(bh * 32 + (n0 >> 6)) * 3 * 6144;
            const int half = (n0 & 63) >> 5;
#pragma unroll
            for (int i = 0; i < 18; ++i) {
                int e = i * 128 + tid;               // 0..2303
                int c = e / 768, rem = e % 768;
                int nr = rem / 192, rem2 = rem % 192, ksl = rem2 >> 5, ln = rem2 & 31;
                int g = ln >> 2, t = ln & 3;
                int tok = nr * 8 + g;                // key - half*32
                int d0 = c * 96 + ksl * 16 + 2 * t;
                float x0 = getf(ystage, sstage, d0,     tok);
                float x1 = getf(ystage, sstage, d0 + 1, tok);
                float x2 = getf(ystage, sstage, d0 + 8, tok);
                float x3 = getf(ystage, sstage, d0 + 9, tok);
                uint32_t* ch = dst + (size_t)c * 6144;
                int go = (((half * 4 + nr) * 6 + ksl) * 32 + ln) * 2;
                *(uint2*)(ch + go)        = make_uint2(pk2b(x0, x1), pk2b(x2, x3));
                *(uint2*)(ch + 3072 + go) = make_uint2(pk2b(bf16res(x0), bf16res(x1)),
                                                       pk2b(bf16res(x2), bf16res(x3)));
            }
        } else {
            // V B-frags: keys n0..n0+31 => ks = half*2 + {0,1}
            uint32_t* dst = VFG + (size_t)(bh * 32 + (n0 >> 6)) * 3 * 6144;
            const int half = (n0 & 63) >> 5;
#pragma unroll
            for (int i = 0; i < 18; ++i) {
                int e = i * 128 + tid;               // 0..2303
                int c = e / 768, rem = e % 768;
                int ntl = rem / 64, rem2 = rem % 64, ksr = rem2 >> 5, ln = rem2 & 31;
                int g = ln >> 2, t = ln & 3;
                int tok0 = ksr * 16 + 2 * t;         // key0 - half*32
                int d = c * 96 + ntl * 8 + g;
                float x0 = getf(ystage, sstage, d, tok0);
                float x1 = getf(ystage, sstage, d, tok0 + 1);
                float x2 = getf(ystage, sstage, d, tok0 + 8);
                float x3 = getf(ystage, sstage, d, tok0 + 9);
                uint32_t* ch = dst + (size_t)c * 6144;
                int go = ((ntl * 4 + (half * 2 + ksr)) * 32 + ln) * 2;
                *(uint2*)(ch + go)        = make_uint2(pk2b(x0, x1), pk2b(x2, x3));
                *(uint2*)(ch + 3072 + go) = make_uint2(pk2b(bf16res(x0), bf16res(x1)),
                                                       pk2b(bf16res(x2), bf16res(x3)));
            }
        }
        __syncthreads();
    }
}

// ============================================================================
// attn8: register-resident FA2, split-bf16 — unchanged (R10/R13 config).
// ============================================================================
#define SM_BYTES (147456 + 3 * 24576 + 64)

__global__ __launch_bounds__(256, 1) void attn8_kernel()
{
    extern __shared__ uint32_t smu[];
    uint32_t* Qh = smu;
    uint32_t* Ql = smu + 18432;
    uint32_t* bufs[3] = { smu + 36864, smu + 43008, smu + 49152 };

    const int tid = threadIdx.x, bh = blockIdx.y, qt = blockIdx.x;
    const int w = tid >> 5, lane = tid & 31, g = lane >> 2, t = lane & 3;

    const uint32_t sb = smem_u32(smu);
    const uint32_t mbase = sb + (36864 + 3 * 6144) * 4;
    const uint32_t mbQ = mbase + 24;

    const uint32_t* KFb = KFG + (size_t)(bh * 32) * 3 * 6144;
    const uint32_t* VFb = VFG + (size_t)(bh * 32) * 3 * 6144;

    if (tid == 0) {
        MB_INIT(mbase + 0, 1); MB_INIT(mbase + 8, 1); MB_INIT(mbase + 16, 1);
        MB_INIT(mbQ, 1);
    }
    __syncthreads();
    if (tid == 0) {
        MB_EXPECT(mbQ, 147456u);
        bulkld(sb, QFG + (size_t)(bh * 8 + qt) * 36864, mbQ, 147456u);
#pragma unroll
        for (int c = 0; c < 3; ++c) {
            MB_EXPECT(mbase + 8 * c, 24576u);
            bulkld(sb + (36864 + c * 6144) * 4, KFb + c * 6144, mbase + 8 * c, 24576u);
        }
    }

    float O[3][12][4];
#pragma unroll
    for (int c = 0; c < 3; ++c)
#pragma unroll
        for (int n = 0; n < 12; ++n)
#pragma unroll
            for (int k = 0; k < 4; ++k) O[c][n][k] = 0.f;
    float mA = -1e30f, mB = -1e30f, lA = 0.f, lB = 0.f;

    MB_WAIT(mbQ, 0);

    for (int kt = 0; kt < 32; ++kt) {
        const uint32_t* VFt = VFb + (size_t)kt * 3 * 6144;
        const uint32_t* KFn = KFb + (size_t)(kt + 1) * 3 * 6144;

        float cS[8][4];
#pragma unroll
        for (int n = 0; n < 8; ++n)
#pragma unroll
            for (int k = 0; k < 4; ++k) cS[n][k] = 0.f;

#pragma unroll
        for (int c = 0; c < 3; ++c) {
            MB_WAIT(mbase + 8 * c, 0);
            const uint32_t* buf = bufs[c];
#pragma unroll
            for (int ksl = 0; ksl < 6; ++ksl) {
                const int ksg = c * 6 + ksl;
                uint4 Ah = *(const uint4*)(Qh + ((w * 18 + ksg) * 32 + lane) * 4);
                uint4 Al = *(const uint4*)(Ql + ((w * 18 + ksg) * 32 + lane) * 4);
#pragma unroll
                for (int n = 0; n < 8; ++n) {
                    uint2 bh2 = *(const uint2*)(buf + ((n * 6 + ksl) * 32 + lane) * 2);
                    uint2 bl2 = *(const uint2*)(buf + 3072 + ((n * 6 + ksl) * 32 + lane) * 2);
                    MMA16(cS[n], Ah.x, Ah.y, Ah.z, Ah.w, bh2.x, bh2.y);
                    MMA16(cS[n], Al.x, Al.y, Al.z, Al.w, bh2.x, bh2.y);
                    MMA16(cS[n], Ah.x, Ah.y, Ah.z, Ah.w, bl2.x, bl2.y);
                }
            }
            __syncthreads();
            if (tid == 0) {
                MB_EXPECT(mbase + 8 * c, 24576u);
                bulkld(sb + (36864 + c * 6144) * 4, VFt + c * 6144, mbase + 8 * c, 24576u);
            }
        }

        float mxA = -1e30f, mxB = -1e30f;
#pragma unroll
        for (int n = 0; n < 8; ++n) {
            mxA = fmaxf(mxA, fmaxf(cS[n][0], cS[n][1]));
            mxB = fmaxf(mxB, fmaxf(cS[n][2], cS[n][3]));
        }
        mxA = fmaxf(mxA, __shfl_xor_sync(0xffffffffu, mxA, 1));
        mxA = fmaxf(mxA, __shfl_xor_sync(0xffffffffu, mxA, 2));
        mxB = fmaxf(mxB, __shfl_xor_sync(0xffffffffu, mxB, 1));
        mxB = fmaxf(mxB, __shfl_xor_sync(0xffffffffu, mxB, 2));
        const float mnA = fmaxf(mA, mxA), mnB = fmaxf(mB, mxB);
        const float alA = __expf(mA - mnA), alB = __expf(mB - mnB);
        mA = mnA; mB = mnB;

        uint32_t PhT[8], PhB[8], PlT[8], PlB[8];
        float sA = 0.f, sB = 0.f;
#pragma unroll
        for (int n = 0; n < 8; ++n) {
            float e0 = __expf(cS[n][0] - mnA), e1 = __expf(cS[n][1] - mnA);
            float e2 = __expf(cS[n][2] - mnB), e3 = __expf(cS[n][3] - mnB);
            sA += e0 + e1; sB += e2 + e3;
            PhT[n] = pk2b(e0, e1); PhB[n] = pk2b(e2, e3);
            PlT[n] = pk2b(bf16res(e0), bf16res(e1));
            PlB[n] = pk2b(bf16res(e2), bf16res(e3));
        }
        sA += __shfl_xor_sync(0xffffffffu, sA, 1);
        sA += __shfl_xor_sync(0xffffffffu, sA, 2);
        sB += __shfl_xor_sync(0xffffffffu, sB, 1);
        sB += __shfl_xor_sync(0xffffffffu, sB, 2);
        lA = lA * alA + sA;
        lB = lB * alB + sB;
#pragma unroll
        for (int c = 0; c < 3; ++c)
#pragma unroll
            for (int n = 0; n < 12; ++n) {
                O[c][n][0] *= alA; O[c][n][1] *= alA;
                O[c][n][2] *= alB; O[c][n][3] *= alB;
            }

#pragma unroll
        for (int c = 0; c < 3; ++c) {
            MB_WAIT(mbase + 8 * c, 1);
            const uint32_t* buf = bufs[c];
#pragma unroll
            for (int ks = 0; ks < 4; ++ks) {
                uint32_t ah0 = PhT[2*ks], ah1 = PhB[2*ks], ah2 = PhT[2*ks+1], ah3 = PhB[2*ks+1];
                uint32_t al0 = PlT[2*ks], al1 = PlB[2*ks], al2 = PlT[2*ks+1], al3 = PlB[2*ks+1];
#pragma unroll
                for (int ntl = 0; ntl < 12; ++ntl) {
                    uint2 vh = *(const uint2*)(buf + ((ntl * 4 + ks) * 32 + lane) * 2);
                    uint2 vl = *(const uint2*)(buf + 3072 + ((ntl * 4 + ks) * 32 + lane) * 2);
                    MMA16(O[c][ntl], ah0, ah1, ah2, ah3, vh.x, vh.y);
                    MMA16(O[c][ntl], al0, al1, al2, al3, vh.x, vh.y);
                    MMA16(O[c][ntl], ah0, ah1, ah2, ah3, vl.x, vl.y);
                }
            }
            __syncthreads();
            if (kt < 31 && tid == 0) {
                MB_EXPECT(mbase + 8 * c, 24576u);
                bulkld(sb + (36864 + c * 6144) * 4, KFn + c * 6144, mbase + 8 * c, 24576u);
            }
        }
    }

    const float liA = 1.f / lA, liB = 1.f / lB;
    const int b = bh >> 3, hh = bh & 7;
    const int rA = qt * 128 + w * 16 + g, rB = rA + 8;
    float* oA = OB + (((size_t)(b * NQ_ + rA)) * 8 + hh) * D_;
    float* oB = OB + (((size_t)(b * NQ_ + rB)) * 8 + hh) * D_;
#pragma unroll
    for (int c = 0; c < 3; ++c)
#pragma unroll
        for (int n = 0; n < 12; ++n) {
            int d = c * 96 + n * 8 + 2 * t;
            *(float2*)(oA + d) = make_float2(O[c][n][0] * liA, O[c][n][1] * liA);
            *(float2*)(oB + d) = make_float2(O[c][n][2] * liB, O[c][n][3] * liB);
        }
}

// ============================================================================
// outproj2 (exact R13/R15 version): 8-token tiles, 256 threads. grid = 512.
// ============================================================================
#define OP_SMEM (2304 * 9 * 4 + 128 * 4)

__global__ void outproj2_kernel(const float* __restrict__ wo_mv, const float* __restrict__ wo_s2mv,
                                const float* __restrict__ wo_mvs2s, const float* __restrict__ wo_s2s,
                                const float* __restrict__ bo_mv, const float* __restrict__ bo_s,
                                float* __restrict__ d_out)
{
    extern __shared__ float xT[];           // [2304][9]
    float* a0sm = xT + 2304 * 9;            // [tok8][o16]
    const int blk = blockIdx.x, tid = threadIdx.x;

    {
        const float4* src = (const float4*)(OB + (size_t)blk * 8 * 2304);
#pragma unroll
        for (int i = 0; i < 18; ++i) {
            int idx = i * 256 + tid;
            int tok = idx / 576, f4 = idx % 576;
            float4 v = src[(size_t)tok * 576 + f4];
            xT[(f4 * 4 + 0) * 9 + tok] = v.x;
            xT[(f4 * 4 + 1) * 9 + tok] = v.y;
            xT[(f4 * 4 + 2) * 9 + tok] = v.z;
            xT[(f4 * 4 + 3) * 9 + tok] = v.w;
        }
    }
    __syncthreads();

    {
        const int tok = tid >> 5, o = (tid >> 1) & 15, part = tid & 1;
        float a = 0.f;
        const float* ws = wo_s2mv + o * 256 + part * 128;
#pragma unroll
        for (int s = 0; s < 128; ++s) {
            int s2 = part * 128 + s;
            int feat = (s2 >> 5) * 288 + 256 + (s2 & 31);
            a += xT[feat * 9 + tok] * ws[s];
        }
        a += __shfl_xor_sync(0xffffffffu, a, 1);
        if (part == 0) a0sm[tok * 16 + o] = a + bo_mv[o];
    }
    __syncthreads();

    const int og = tid >> 3, tok = tid & 7;
    const int tglob = blk * 8 + tok;

#pragma unroll
    for (int j = 0; j < 8; ++j) {
        const int outIdx = j * 32 + og;
        const int o = outIdx >> 4, x = outIdx & 15;
        const int gg = GRADE_RT[x];
        const float* wp = wo_mv + (size_t)o * 640 + gg;
        float y = (x == 0) ? a0sm[tok * 16 + o] : 0.f;
#pragma unroll 16
        for (int i = 0; i < 128; ++i) {
            int feat = (i >> 4) * 288 + (i & 15) * 16 + x;
            y += xT[feat * 9 + tok] * wp[i * 5];
        }
        d_out[(size_t)tglob * 256 + outIdx] = y;
    }
    {
        const int s = og;
        float y = bo_s[s];
        const float* wm = wo_mvs2s + s * 128;
#pragma unroll 16
        for (int i = 0; i < 128; ++i) {
            int feat = (i >> 4) * 288 + (i & 15) * 16;
            y += xT[feat * 9 + tok] * wm[i];
        }
        const float* ws = wo_s2s + s * 256;
#pragma unroll 16
        for (int s2 = 0; s2 < 256; ++s2) {
            int feat = (s2 >> 5) * 288 + 256 + (s2 & 31);
            y += xT[feat * 9 + tok] * ws[s2];
        }
        d_out[(size_t)B_ * NQ_ * 256 + (size_t)tglob * 32 + s] = y;
    }
}

extern "C" void kernel_launch(void* const* d_in, const int* in_sizes, int n_in,
                              void* d_out, int out_size)
{
    (void)in_sizes; (void)n_in; (void)out_size;
    const float* mv_kv = (const float*)d_in[0];
    const float* mv_q  = (const float*)d_in[1];
    const float* s_kv  = (const float*)d_in[2];
    const float* s_q   = (const float*)d_in[3];
    const float* wq_mv = (const float*)d_in[4],  *wq_s2mv = (const float*)d_in[5];
    const float* wq_m2s = (const float*)d_in[6], *wq_s2s = (const float*)d_in[7];
    const float* bq_mv = (const float*)d_in[8],  *bq_s = (const float*)d_in[9];
    const float* wk_mv = (const float*)d_in[10], *wk_s2mv = (const float*)d_in[11];
    const float* wk_m2s = (const float*)d_in[12],*wk_s2s = (const float*)d_in[13];
    const float* bk_mv = (const float*)d_in[14], *bk_s = (const float*)d_in[15];
    const float* wv_mv = (const float*)d_in[16], *wv_s2mv = (const float*)d_in[17];
    const float* wv_m2s = (const float*)d_in[18],*wv_s2s = (const float*)d_in[19];
    const float* bv_mv = (const float*)d_in[20], *bv_s = (const float*)d_in[21];
    const float* wo_mv = (const float*)d_in[22], *wo_s2mv = (const float*)d_in[23];
    const float* wo_m2s = (const float*)d_in[24],*wo_s2s = (const float*)d_in[25];
    const float* bo_mv = (const float*)d_in[26], *bo_s = (const float*)d_in[27];

    cudaFuncSetAttribute(proj4_kernel, cudaFuncAttributeMaxDynamicSharedMemorySize, P4_SMEM);
    cudaFuncSetAttribute(attn8_kernel, cudaFuncAttributeMaxDynamicSharedMemorySize, SM_BYTES);
    cudaFuncSetAttribute(outproj2_kernel, cudaFuncAttributeMaxDynamicSharedMemorySize, OP_SMEM);

    proj4_kernel<<<dim3(256, 3), 128, P4_SMEM>>>(
        mv_q, s_q, mv_kv, s_kv,
        wq_mv, wq_s2mv, wq_m2s, wq_s2s, bq_mv, bq_s,
        wk_mv, wk_s2mv, wk_m2s, wk_s2s, bk_mv, bk_s,
        wv_mv, wv_s2mv, wv_m2s, wv_s2s, bv_mv, bv_s);
    attn8_kernel<<<dim3(8, 32), 256, SM_BYTES>>>();
    outproj2_kernel<<<512, 256, OP_SMEM>>>(wo_mv, wo_s2mv, wo_m2s, wo_s2s, bo_mv, bo_s,
                                           (float*)d_out);
}